// round 15
// baseline (speedup 1.0000x reference)
#include <cuda_runtime.h>
#include <cuda_bf16.h>
#include <math.h>
#include <cstdint>

#define NEDGE 65536
#define NATOM 2048
#define NRADB 24
#define NCOMP 5
#define KTOT  69
#define FDIM  216            // 24 * 9
#define EMBD  16
#define TILE  32
#define NSPEC 94

// ---------------- scratch (static device globals) ----------------
__device__ int   g_lx[KTOT], g_ly[KTOT], g_lz[KTOT], g_izk[KTOT];
__device__ float g_fnorm[KTOT], g_lam[KTOT];
__constant__ int KOFF[5] = {0, 4, 14, 34, 69};

__device__ int   d_seg[NATOM + 1];
__device__ float d_feat[NATOM * FDIM];
__device__ float d_h1[NATOM * 256];
__device__ float d_h2[NATOM * 128];
// edge-pipeline scratch
__device__ __nv_bfloat16 d_hh[NEDGE * 64];
__device__ __nv_bfloat16 d_hl[NEDGE * 64];
__device__ float d_gv[NEDGE * 72];
__device__ float d_rad[NEDGE * 120];
__device__ __nv_bfloat16 d_Bt2_hi[128 * 64];
__device__ __nv_bfloat16 d_Bt2_lo[128 * 64];
__device__ float d_br2p[120];
// species-contraction scratch
__device__ float d_semb[NSPEC * EMBD];
__device__ float d_Ws[NSPEC * FDIM * 256];   // 20.8 MB
__device__ int   d_soff[NSPEC + 1];
__device__ int   d_satoms[NATOM];

__device__ __forceinline__ float silu_f(float x) { return x / (1.f + expf(-x)); }

__device__ __forceinline__ float powi(float b, int l) {
    float r = 1.f;
#pragma unroll
    for (int i = 0; i < 4; i++) if (i < l) r *= b;
    return r;
}

// bf16 mma.sync (family-portable; legacy HMMA pipe on Blackwell)
__device__ __forceinline__ void mma16816(float* c, const uint32_t* a, const uint32_t* b) {
    asm volatile(
        "mma.sync.aligned.m16n8k16.row.col.f32.bf16.bf16.f32 "
        "{%0,%1,%2,%3}, {%4,%5,%6,%7}, {%8,%9}, {%0,%1,%2,%3};"
        : "+f"(c[0]), "+f"(c[1]), "+f"(c[2]), "+f"(c[3])
        : "r"(a[0]), "r"(a[1]), "r"(a[2]), "r"(a[3]), "r"(b[0]), "r"(b[1]));
}

__device__ __forceinline__ void ldsm4(uint32_t* r, uint32_t addr) {
    asm volatile("ldmatrix.sync.aligned.m8n8.x4.shared.b16 {%0,%1,%2,%3}, [%4];"
                 : "=r"(r[0]), "=r"(r[1]), "=r"(r[2]), "=r"(r[3]) : "r"(addr));
}

__device__ __forceinline__ uint32_t smem_u32(const void* p) {
    uint32_t a;
    asm("{ .reg .u64 t; cvta.to.shared.u64 t, %1; cvt.u32.u64 %0, t; }" : "=r"(a) : "l"(p));
    return a;
}

// ---------------- table init ----------------
__global__ void init_tables() {
    if (threadIdx.x == 0 && blockIdx.x == 0) {
        const int fact[5] = {1, 1, 2, 6, 24};
        int idx = 0;
        for (int iz = 0; iz < 4; iz++) {
            int z = iz + 1;
            for (int n = 0; n <= z; n++)
                for (int lx = 0; lx <= n; lx++)
                    for (int ly = 0; ly <= n - lx; ly++) {
                        int lz = n - lx - ly;
                        g_lx[idx] = lx; g_ly[idx] = ly; g_lz[idx] = lz;
                        g_izk[idx] = iz;
                        g_fnorm[idx] = (float)fact[z] /
                            (float)(fact[z - n] * fact[lx] * fact[ly] * fact[lz]);
                        g_lam[idx] = (n & 1) ? -1.f : 1.f;
                        idx++;
                    }
        }
    }
}

// ---------------- segment offsets ----------------
__global__ void seg_kernel(const int* __restrict__ fia) {
    int a = blockIdx.x * blockDim.x + threadIdx.x;
    if (a <= NATOM) {
        int lo = 0, hi = NEDGE;
        while (lo < hi) {
            int mid = (lo + hi) >> 1;
            if (fia[mid] < a) lo = mid + 1; else hi = mid;
        }
        d_seg[a] = lo;
    }
}

// ---------------- Wr2 -> permuted-transposed bf16 hi/lo [128 n][64 k] ----------------
__global__ void conv_w2_kernel(const float* __restrict__ Wr2, const float* __restrict__ br2) {
    int i = blockIdx.x * blockDim.x + threadIdx.x;
    if (i < 128 * 64) {
        int n = i >> 6, k = i & 63;
        float v = 0.f;
        if (n < 120) {
            int j = (n % 24) * 5 + n / 24;
            v = Wr2[k * 120 + j];
        }
        __nv_bfloat16 h = __float2bfloat16(v);
        d_Bt2_hi[i] = h;
        d_Bt2_lo[i] = __float2bfloat16(v - __bfloat162float(h));
        if (k == 0 && n < 120) d_br2p[n] = br2[(n % 24) * 5 + n / 24];
    }
}

// ---------------- edge kernel: geometry + basis + MLP1 + angular ----------------
__global__ __launch_bounds__(256) void edge_kernel(
    const float* __restrict__ rij,
    const float* __restrict__ Wr1, const float* __restrict__ br1)
{
    __shared__ float Wr1s[NRADB * 64];
    __shared__ float br1s[64];
    __shared__ float basw_s[8][96];
    __shared__ int   slk[KTOT];
    __shared__ float sfn[KTOT];

    int tid = threadIdx.x;
    int wid = tid >> 5, lane = tid & 31;

    for (int i = tid; i < NRADB * 64; i += 256) Wr1s[i] = Wr1[i];
    if (tid < 64) br1s[tid] = br1[tid];
    if (tid < KTOT) {
        slk[tid] = g_lx[tid] | (g_ly[tid] << 8) | (g_lz[tid] << 16);
        sfn[tid] = g_fnorm[tid];
    }
    __syncthreads();

    int e0 = blockIdx.x * 32 + wid * 4;
    float* basw = basw_s[wid];

    float rE = 0.f, uxE = 0.f, uyE = 0.f, uzE = 0.f, fcE = 0.f;
    if (lane < 4) {
        int e = e0 + lane;
        float x = rij[e * 3], y = rij[e * 3 + 1], z = rij[e * 3 + 2];
        float r = sqrtf(x * x + y * y + z * z);
        float inv = 1.f / r;
        rE = r;
        uxE = x * inv + 1e-12f;
        uyE = y * inv + 1e-12f;
        uzE = z * inv + 1e-12f;
        float rc = fminf(r, 6.f);
        fcE = 0.5f * (cosf(rc * 0.52359877559829887f) + 1.f);
    }
    {
        int ge = lane >> 3;
        float rB  = __shfl_sync(0xffffffffu, rE, ge);
        float fcB = __shfl_sync(0xffffffffu, fcE, ge);
#pragma unroll
        for (int q = 0; q < 3; q++) {
            int k = (lane & 7) + q * 8;
            float d = rB - (6.f / 23.f) * (float)k;
            basw[ge * 24 + k] = expf(-8.f * d * d) * fcB;
        }
    }
    __syncwarp();
    {
        float a0[4], a1[4];
#pragma unroll
        for (int e = 0; e < 4; e++) { a0[e] = 0.f; a1[e] = 0.f; }
#pragma unroll 6
        for (int k = 0; k < NRADB; k++) {
            float2 w = *(const float2*)&Wr1s[k * 64 + 2 * lane];
            float b0 = basw[k], b1 = basw[24 + k], b2 = basw[48 + k], b3 = basw[72 + k];
            a0[0] += b0 * w.x; a1[0] += b0 * w.y;
            a0[1] += b1 * w.x; a1[1] += b1 * w.y;
            a0[2] += b2 * w.x; a1[2] += b2 * w.y;
            a0[3] += b3 * w.x; a1[3] += b3 * w.y;
        }
        float2 bb = *(const float2*)&br1s[2 * lane];
#pragma unroll
        for (int e = 0; e < 4; e++) {
            float h0 = silu_f(a0[e] + bb.x);
            float h1 = silu_f(a1[e] + bb.y);
            __nv_bfloat16 H0 = __float2bfloat16(h0);
            __nv_bfloat16 H1 = __float2bfloat16(h1);
            size_t off = (size_t)(e0 + e) * 64 + 2 * lane;
            *(__nv_bfloat162*)&d_hh[off] = __halves2bfloat162(H0, H1);
            *(__nv_bfloat162*)&d_hl[off] = __halves2bfloat162(
                __float2bfloat16(h0 - __bfloat162float(H0)),
                __float2bfloat16(h1 - __bfloat162float(H1)));
        }
    }
#pragma unroll
    for (int e4 = 0; e4 < 4; e4++) {
        float ux = __shfl_sync(0xffffffffu, uxE, e4);
        float uy = __shfl_sync(0xffffffffu, uyE, e4);
        float uz = __shfl_sync(0xffffffffu, uzE, e4);
#pragma unroll
        for (int q = 0; q < 3; q++) {
            int k = lane + q * 32;
            if (k < KTOT) {
                int pk = slk[k];
                d_gv[(size_t)(e0 + e4) * 72 + k] = sfn[k] *
                    powi(ux, pk & 255) * powi(uy, (pk >> 8) & 255) * powi(uz, pk >> 16);
            }
        }
    }
}

// ---------------- MLP2 GEMM: rad = silu(h @ Wr2p + b), 3-pass bf16 split ----------------
// BM=64 for occupancy (smem 54KB, launch_bounds(256,3) -> ~24 warps/SM).
// Warp tile m16 x n64: warps 0-3 -> n[0:64), warps 4-7 -> n[64:128), m0=(w&3)*16.
#define E2_LDA 72        // elems; row stride 144 B (16B-aligned, ldsm conflict-free)
#define E2_AH 0
#define E2_AL 9216
#define E2_BH 18432
#define E2_BL 36864
#define E2_SMEM 55296
__global__ __launch_bounds__(256, 3) void mlp2_gemm_kernel(
    const __nv_bfloat16* __restrict__ hh, const __nv_bfloat16* __restrict__ hl,
    float* __restrict__ rad)
{
    extern __shared__ char smem[];
    uint32_t sb = smem_u32(smem);
    int tid = threadIdx.x;
    int warp = tid >> 5, lane = tid & 31;
    int e0 = blockIdx.x * 64;

    // load A (h tile 64x64) and B (Wr2p 128x64)
    for (int i = tid; i < 512; i += 256) {
        int row = i >> 3, ch = i & 7;
        size_t ga = (size_t)(e0 + row) * 64 + ch * 8;
        *(uint4*)(smem + E2_AH + row * 144 + ch * 16) = *(const uint4*)(hh + ga);
        *(uint4*)(smem + E2_AL + row * 144 + ch * 16) = *(const uint4*)(hl + ga);
    }
    for (int i = tid; i < 1024; i += 256) {
        int row = i >> 3, ch = i & 7;
        *(uint4*)(smem + E2_BH + row * 144 + ch * 16) = *(const uint4*)(d_Bt2_hi + row * 64 + ch * 8);
        *(uint4*)(smem + E2_BL + row * 144 + ch * 16) = *(const uint4*)(d_Bt2_lo + row * 64 + ch * 8);
    }
    __syncthreads();

    int m0 = (warp & 3) * 16;
    int n0 = (warp >> 2) * 64;
    int lrow = (lane & 7) + ((lane >> 3) & 1) * 8;
    int lcol = (lane >> 4) * 8;

    float acc[8][4];
#pragma unroll
    for (int j = 0; j < 8; j++)
#pragma unroll
        for (int q = 0; q < 4; q++) acc[j][q] = 0.f;

#pragma unroll
    for (int kst = 0; kst < 4; kst++) {
        int kcol = kst * 16 + lcol;
        uint32_t ah[4], al[4];
        ldsm4(ah, sb + E2_AH + ((m0 + lrow) * E2_LDA + kcol) * 2);
        ldsm4(al, sb + E2_AL + ((m0 + lrow) * E2_LDA + kcol) * 2);
#pragma unroll
        for (int nb = 0; nb < 4; nb++) {
            uint32_t th[4], tl[4];
            ldsm4(th, sb + E2_BH + ((n0 + nb * 16 + lrow) * E2_LDA + kcol) * 2);
            ldsm4(tl, sb + E2_BL + ((n0 + nb * 16 + lrow) * E2_LDA + kcol) * 2);
            uint32_t b0h[2] = {th[0], th[2]}, b1h[2] = {th[1], th[3]};
            uint32_t b0l[2] = {tl[0], tl[2]}, b1l[2] = {tl[1], tl[3]};
            mma16816(acc[2 * nb],     ah, b0h);
            mma16816(acc[2 * nb],     al, b0h);
            mma16816(acc[2 * nb],     ah, b0l);
            mma16816(acc[2 * nb + 1], ah, b1h);
            mma16816(acc[2 * nb + 1], al, b1h);
            mma16816(acc[2 * nb + 1], ah, b1l);
        }
    }

    // epilogue: silu + bias for cols < 120
    int gid = lane >> 2, tig = lane & 3;
    int r0 = e0 + m0 + gid;
#pragma unroll
    for (int j = 0; j < 8; j++) {
        int cn = n0 + j * 8 + tig * 2;
        if (cn < 120) {
            float b0 = d_br2p[cn], b1 = d_br2p[cn + 1];
            *(float2*)(rad + (size_t)r0 * 120 + cn) =
                make_float2(silu_f(acc[j][0] + b0), silu_f(acc[j][1] + b1));
            *(float2*)(rad + (size_t)(r0 + 8) * 120 + cn) =
                make_float2(silu_f(acc[j][2] + b0), silu_f(acc[j][3] + b1));
        }
    }
}

// ---------------- per-atom moment kernel: stage + phase B + feature epilogue ----------------
__global__ __launch_bounds__(256) void moment_kernel(
    const float* __restrict__ rad, const float* __restrict__ gv)
{
    __shared__ float rads[TILE * 120];
    __shared__ float gvs[TILE * 72];
    __shared__ float gis[70 * 24];

    int tid = threadIdx.x;
    int a = blockIdx.x;

    bool actB = tid < 210;
    int kB = tid / 3, r0B = (tid % 3) * 8, cB = 0;
    if (actB) cB = (kB < 4) ? 1 : (kB < 14) ? 2 : (kB < 34) ? 3 : (kB < 69) ? 4 : 0;
    float accB[8];
#pragma unroll
    for (int q = 0; q < 8; q++) accB[q] = 0.f;

    int beg = d_seg[a], end = d_seg[a + 1];

    for (int pos = beg; pos < end; pos += TILE) {
        int nE = min(TILE, end - pos);
        for (int i = tid; i < nE * 30; i += 256) {
            int row = i / 30, ch = i % 30;
            *(float4*)&rads[row * 120 + ch * 4] =
                *(const float4*)(rad + (size_t)(pos + row) * 120 + ch * 4);
        }
        for (int i = tid; i < nE * 18; i += 256) {
            int row = i / 18, ch = i % 18;
            *(float4*)&gvs[row * 72 + ch * 4] =
                *(const float4*)(gv + (size_t)(pos + row) * 72 + ch * 4);
        }
        __syncthreads();
        if (actB) {
            int base = cB * 24 + r0B;
            for (int e = 0; e < nE; e++) {
                float g = (kB < KTOT) ? gvs[e * 72 + kB] : 1.f;
                const float4* rp = (const float4*)&rads[e * 120 + base];
                float4 p0 = rp[0], p1 = rp[1];
                accB[0] += g * p0.x; accB[1] += g * p0.y;
                accB[2] += g * p0.z; accB[3] += g * p0.w;
                accB[4] += g * p1.x; accB[5] += g * p1.y;
                accB[6] += g * p1.z; accB[7] += g * p1.w;
            }
        }
        __syncthreads();
    }

    if (actB) {
#pragma unroll
        for (int q = 0; q < 8; q++) gis[kB * 24 + r0B + q] = accB[q];
    }
    __syncthreads();

    if (tid < FDIM) {
        int grp = tid / NRADB, r = tid % NRADB;
        float v;
        if (grp == 0) {
            v = gis[KTOT * 24 + r];
        } else {
            int iz = (grp - 1) >> 1;
            int neg = (grp - 1) & 1;
            float ssum = 0.f;
            for (int k = KOFF[iz]; k < KOFF[iz + 1]; k++) {
                float g = gis[k * 24 + r];
                ssum += g * g * (neg ? g_lam[k] : 1.f);
            }
            v = ssum * (1.0f / (float)(1 << iz));
        }
        d_feat[a * FDIM + tid] = v;
    }
}

// ---------------- species embeddings for all 94 species ----------------
__global__ void sembed_kernel(
    const float* __restrict__ Ws1, const float* __restrict__ bs1,
    const float* __restrict__ Ws2, const float* __restrict__ bs2)
{
    int s = blockIdx.x, lane = threadIdx.x;
    __shared__ float hsp[32];
    hsp[lane] = silu_f(Ws1[s * 32 + lane] + bs1[lane]);
    __syncwarp();
    if (lane < EMBD) {
        float acc = bs2[lane];
#pragma unroll
        for (int i = 0; i < 32; i++) acc += hsp[i] * Ws2[i * EMBD + lane];
        d_semb[s * EMBD + lane] = acc;
    }
}

// ---------------- W_s[f][n] = sum_e semb[s][e] * Wa1[f*16+e][n] ----------------
// grid (216, 2), 128 threads; Wa1 block read ONCE, looped over all species.
__global__ __launch_bounds__(128) void wspec_kernel(const float* __restrict__ Wa1) {
    __shared__ float wblk[16][128];
    __shared__ float sembs[NSPEC * EMBD];
    int f = blockIdx.x, n0 = blockIdx.y * 128;
    int tid = threadIdx.x;
#pragma unroll
    for (int e = 0; e < 16; e++)
        wblk[e][tid] = Wa1[(size_t)(f * 16 + e) * 256 + n0 + tid];
    for (int i = tid; i < NSPEC * EMBD; i += 128) sembs[i] = d_semb[i];
    __syncthreads();
    for (int s = 0; s < NSPEC; s++) {
        float acc = 0.f;
#pragma unroll
        for (int e = 0; e < 16; e++) acc += sembs[s * EMBD + e] * wblk[e][tid];
        d_Ws[((size_t)s * FDIM + f) * 256 + n0 + tid] = acc;
    }
}

// ---------------- group atoms by species (counting sort, 1 CTA) ----------------
__global__ void group_kernel(const int* __restrict__ species) {
    __shared__ int cnt[NSPEC], off[NSPEC + 1], pos[NSPEC];
    int tid = threadIdx.x;
    if (tid < NSPEC) cnt[tid] = 0;
    __syncthreads();
    for (int a = tid; a < NATOM; a += 256) atomicAdd(&cnt[species[a]], 1);
    __syncthreads();
    if (tid == 0) {
        int r = 0;
        for (int s = 0; s < NSPEC; s++) { off[s] = r; r += cnt[s]; }
        off[NSPEC] = r;
    }
    __syncthreads();
    if (tid < NSPEC) pos[tid] = off[tid];
    if (tid <= NSPEC) d_soff[tid] = off[tid];
    __syncthreads();
    for (int a = tid; a < NATOM; a += 256) {
        int p = atomicAdd(&pos[species[a]], 1);
        d_satoms[p] = a;
    }
}

// ---------------- species GEMM: h1[a] = silu(feat[a] @ W_s + ba1), fp32 exact ----------------
// grid (94, 2), 256 threads = 128 n x 2 k-halves. Atoms chunked by 8.
__global__ __launch_bounds__(256) void species_gemm_kernel(const float* __restrict__ ba1) {
    __shared__ float feats[8][FDIM];
    __shared__ float partial[8][128];
    __shared__ int atoms_s[8];
    int tid = threadIdx.x;
    int s = blockIdx.x;
    int nloc = tid & 127;
    int n = blockIdx.y * 128 + nloc;
    int kh = tid >> 7;                       // 0/1 -> K range kh*108 .. +108
    int beg = d_soff[s], end = d_soff[s + 1];
    float bias = ba1[n];

    for (int p = beg; p < end; p += 8) {
        int nc = min(8, end - p);
        for (int i = tid; i < 8 * FDIM; i += 256) {
            int a8 = i / FDIM, k = i % FDIM;
            feats[a8][k] = (a8 < nc) ? d_feat[(size_t)d_satoms[p + a8] * FDIM + k] : 0.f;
        }
        if (tid < 8) atoms_s[tid] = (tid < nc) ? d_satoms[p + tid] : -1;
        __syncthreads();

        float acc[8];
#pragma unroll
        for (int a = 0; a < 8; a++) acc[a] = 0.f;
        const float* wp = d_Ws + ((size_t)s * FDIM + kh * 108) * 256 + n;
#pragma unroll 4
        for (int k = 0; k < 108; k++) {
            float w = wp[(size_t)k * 256];
            int kk = kh * 108 + k;
#pragma unroll
            for (int a = 0; a < 8; a++) acc[a] += feats[a][kk] * w;
        }
        if (kh == 1) {
#pragma unroll
            for (int a = 0; a < 8; a++) partial[a][nloc] = acc[a];
        }
        __syncthreads();
        if (kh == 0) {
#pragma unroll
            for (int a = 0; a < 8; a++) {
                if (a < nc) {
                    float v = acc[a] + partial[a][nloc] + bias;
                    d_h1[(size_t)atoms_s[a] * 256 + n] = silu_f(v);
                }
            }
        }
        __syncthreads();
    }
}

// ---------------- fp32 GEMM2 + bias + silu (128 CTAs) ----------------
__global__ __launch_bounds__(256) void gemm_silu_k(
    const float* __restrict__ A, const float* __restrict__ B,
    const float* __restrict__ bias, float* __restrict__ C,
    int M, int N, int K)
{
    const int BM = 32, BN = 64, BK = 32;
    __shared__ float As[BK][BM + 1];
    __shared__ float Bs[BK][BN + 1];
    int tid = threadIdx.x;
    int tx = tid & 15, ty = tid >> 4;   // 16 x 16
    int row0 = blockIdx.x * BM, col0 = blockIdx.y * BN;
    float accum[2][4];
#pragma unroll
    for (int i = 0; i < 2; i++)
#pragma unroll
        for (int j = 0; j < 4; j++) accum[i][j] = 0.f;

    for (int k0 = 0; k0 < K; k0 += BK) {
        for (int i = tid; i < BM * BK; i += 256) {
            int m = i / BK, k = i % BK;
            As[k][m] = A[(size_t)(row0 + m) * K + k0 + k];
        }
        for (int i = tid; i < BK * BN; i += 256) {
            int k = i / BN, n = i % BN;
            Bs[k][n] = B[(size_t)(k0 + k) * N + col0 + n];
        }
        __syncthreads();
#pragma unroll
        for (int k = 0; k < BK; k++) {
            float av[2], bv[4];
#pragma unroll
            for (int i = 0; i < 2; i++) av[i] = As[k][ty * 2 + i];
#pragma unroll
            for (int j = 0; j < 4; j++) bv[j] = Bs[k][tx * 4 + j];
#pragma unroll
            for (int i = 0; i < 2; i++)
#pragma unroll
                for (int j = 0; j < 4; j++) accum[i][j] += av[i] * bv[j];
        }
        __syncthreads();
    }
#pragma unroll
    for (int i = 0; i < 2; i++) {
        int row = row0 + ty * 2 + i;
#pragma unroll
        for (int j = 0; j < 4; j++) {
            int col = col0 + tx * 4 + j;
            C[(size_t)row * N + col] = silu_f(accum[i][j] + bias[col]);
        }
    }
}

// ---------------- final reduction ----------------
__global__ void zero_out_k(float* out) { out[0] = 0.f; }

__global__ void final_kernel(const float* __restrict__ Wa3,
                             const float* __restrict__ ba3, float* out) {
    int gt = blockIdx.x * blockDim.x + threadIdx.x;
    int a = gt >> 5, lane = gt & 31;
    if (a < NATOM) {
        float s = 0.f;
#pragma unroll
        for (int i = lane; i < 128; i += 32) s += d_h2[a * 128 + i] * Wa3[i];
#pragma unroll
        for (int o = 16; o; o >>= 1) s += __shfl_xor_sync(0xffffffffu, s, o);
        if (lane == 0) atomicAdd(out, s + ba3[0]);
    }
}

// ---------------- launch ----------------
extern "C" void kernel_launch(void* const* d_in, const int* in_sizes, int n_in,
                              void* d_out, int out_size) {
    (void)in_sizes; (void)n_in; (void)out_size;
    const float* rij = (const float*)d_in[0];
    const float* Wr1 = (const float*)d_in[1];
    const float* br1 = (const float*)d_in[2];
    const float* Wr2 = (const float*)d_in[3];
    const float* br2 = (const float*)d_in[4];
    const float* Ws1 = (const float*)d_in[5];
    const float* bs1 = (const float*)d_in[6];
    const float* Ws2 = (const float*)d_in[7];
    const float* bs2 = (const float*)d_in[8];
    const float* Wa1 = (const float*)d_in[9];
    const float* ba1 = (const float*)d_in[10];
    const float* Wa2 = (const float*)d_in[11];
    const float* ba2 = (const float*)d_in[12];
    const float* Wa3 = (const float*)d_in[13];
    const float* ba3 = (const float*)d_in[14];
    const int*   fia     = (const int*)d_in[15];
    const int*   species = (const int*)d_in[16];
    float* out = (float*)d_out;

    void *p_feat, *p_h1, *p_h2, *p_hh, *p_hl, *p_gv, *p_rad;
    cudaGetSymbolAddress(&p_feat, d_feat);
    cudaGetSymbolAddress(&p_h1,   d_h1);
    cudaGetSymbolAddress(&p_h2,   d_h2);
    cudaGetSymbolAddress(&p_hh,   d_hh);
    cudaGetSymbolAddress(&p_hl,   d_hl);
    cudaGetSymbolAddress(&p_gv,   d_gv);
    cudaGetSymbolAddress(&p_rad,  d_rad);

    init_tables<<<1, 1>>>();                                        // 0
    conv_w2_kernel<<<(128 * 64 + 255) / 256, 256>>>(Wr2, br2);      // 1
    edge_kernel<<<NEDGE / 32, 256>>>(rij, Wr1, br1);                // 2

    cudaFuncSetAttribute(mlp2_gemm_kernel, cudaFuncAttributeMaxDynamicSharedMemorySize, E2_SMEM);
    mlp2_gemm_kernel<<<NEDGE / 64, 256, E2_SMEM>>>(                 // 3 (profiled)
        (const __nv_bfloat16*)p_hh, (const __nv_bfloat16*)p_hl, (float*)p_rad);

    seg_kernel<<<(NATOM + 1 + 255) / 256, 256>>>(fia);              // 4
    moment_kernel<<<NATOM, 256>>>((const float*)p_rad, (const float*)p_gv);  // 5

    sembed_kernel<<<NSPEC, 32>>>(Ws1, bs1, Ws2, bs2);               // 6
    wspec_kernel<<<dim3(FDIM, 2), 128>>>(Wa1);                      // 7
    group_kernel<<<1, 256>>>(species);                              // 8
    species_gemm_kernel<<<dim3(NSPEC, 2), 256>>>(ba1);              // 9

    gemm_silu_k<<<dim3(NATOM / 32, 128 / 64), 256>>>(
        (const float*)p_h1, Wa2, ba2, (float*)p_h2, NATOM, 128, 256);

    zero_out_k<<<1, 1>>>(out);
    final_kernel<<<NATOM * 32 / 256, 256>>>(Wa3, ba3, out);
}

// round 16
// speedup vs baseline: 1.0143x; 1.0143x over previous
#include <cuda_runtime.h>
#include <cuda_bf16.h>
#include <math.h>
#include <cstdint>

#define NEDGE 65536
#define NATOM 2048
#define NRADB 24
#define NCOMP 5
#define KTOT  69
#define FDIM  216            // 24 * 9
#define EMBD  16
#define TILE  32
#define KTOTAL 3456          // FDIM * EMBD
#define KSPLIT 4
#define ITERS  27            // KTOTAL / KSPLIT / 32

// ---------------- scratch (static device globals) ----------------
__constant__ int KOFF[5] = {0, 4, 14, 34, 69};

__device__ float d_emb[NATOM * EMBD];
__device__ float d_feat[NATOM * FDIM];
__device__ float d_h1parts[KSPLIT * NATOM * 256];
__device__ float d_h1[NATOM * 256];
__device__ float d_h2[NATOM * 128];
__device__ __nv_bfloat16 d_Bt_hi[256 * KTOTAL];
__device__ __nv_bfloat16 d_Bt_lo[256 * KTOTAL];
__device__ __nv_bfloat16 d_Xh[NATOM * KTOTAL];
__device__ __nv_bfloat16 d_Xl[NATOM * KTOTAL];
// edge-pipeline scratch
__device__ __nv_bfloat16 d_hh[NEDGE * 64];
__device__ __nv_bfloat16 d_hl[NEDGE * 64];
__device__ float d_gv[NEDGE * 72];
__device__ float d_rad[NEDGE * 120];
__device__ __nv_bfloat16 d_Bt2_hi[128 * 64];
__device__ __nv_bfloat16 d_Bt2_lo[128 * 64];
__device__ float d_br2p[120];

__device__ __forceinline__ float silu_f(float x) { return x / (1.f + expf(-x)); }

__device__ __forceinline__ float powi(float b, int l) {
    float r = 1.f;
#pragma unroll
    for (int i = 0; i < 4; i++) if (i < l) r *= b;
    return r;
}

// build lxlylz tables into smem (single thread; overlapped with other warps' loads)
__device__ __forceinline__ void build_tab(int* slk, float* sfn, float* slam) {
    const int fact[5] = {1, 1, 2, 6, 24};
    int idx = 0;
    for (int iz = 0; iz < 4; iz++) {
        int z = iz + 1;
        for (int n = 0; n <= z; n++)
            for (int lx = 0; lx <= n; lx++)
                for (int ly = 0; ly <= n - lx; ly++) {
                    int lz = n - lx - ly;
                    if (slk) slk[idx] = lx | (ly << 8) | (lz << 16);
                    if (sfn) sfn[idx] = (float)fact[z] /
                        (float)(fact[z - n] * fact[lx] * fact[ly] * fact[lz]);
                    if (slam) slam[idx] = (n & 1) ? -1.f : 1.f;
                    idx++;
                }
    }
}

// bf16 mma.sync (family-portable; legacy HMMA pipe on Blackwell)
__device__ __forceinline__ void mma16816(float* c, const uint32_t* a, const uint32_t* b) {
    asm volatile(
        "mma.sync.aligned.m16n8k16.row.col.f32.bf16.bf16.f32 "
        "{%0,%1,%2,%3}, {%4,%5,%6,%7}, {%8,%9}, {%0,%1,%2,%3};"
        : "+f"(c[0]), "+f"(c[1]), "+f"(c[2]), "+f"(c[3])
        : "r"(a[0]), "r"(a[1]), "r"(a[2]), "r"(a[3]), "r"(b[0]), "r"(b[1]));
}

__device__ __forceinline__ void ldsm4(uint32_t* r, uint32_t addr) {
    asm volatile("ldmatrix.sync.aligned.m8n8.x4.shared.b16 {%0,%1,%2,%3}, [%4];"
                 : "=r"(r[0]), "=r"(r[1]), "=r"(r[2]), "=r"(r[3]) : "r"(addr));
}

__device__ __forceinline__ uint32_t smem_u32(const void* p) {
    uint32_t a;
    asm("{ .reg .u64 t; cvta.to.shared.u64 t, %1; cvt.u32.u64 %0, t; }" : "=r"(a) : "l"(p));
    return a;
}

__device__ __forceinline__ int seg_lower_bound(const int* fia, int a) {
    int lo = 0, hi = NEDGE;
    while (lo < hi) {
        int mid = (lo + hi) >> 1;
        if (fia[mid] < a) lo = mid + 1; else hi = mid;
    }
    return lo;
}

// ---------------- Wr2 -> permuted-transposed bf16 hi/lo [128 n][64 k] ----------------
__global__ void conv_w2_kernel(const float* __restrict__ Wr2, const float* __restrict__ br2) {
    int i = blockIdx.x * blockDim.x + threadIdx.x;
    if (i < 128 * 64) {
        int n = i >> 6, k = i & 63;
        float v = 0.f;
        if (n < 120) {
            int j = (n % 24) * 5 + n / 24;
            v = Wr2[k * 120 + j];
        }
        __nv_bfloat16 h = __float2bfloat16(v);
        d_Bt2_hi[i] = h;
        d_Bt2_lo[i] = __float2bfloat16(v - __bfloat162float(h));
        if (k == 0 && n < 120) d_br2p[n] = br2[(n % 24) * 5 + n / 24];
    }
}

// ---------------- edge kernel: geometry + basis + MLP1 + angular ----------------
__global__ __launch_bounds__(256) void edge_kernel(
    const float* __restrict__ rij,
    const float* __restrict__ Wr1, const float* __restrict__ br1)
{
    __shared__ float Wr1s[NRADB * 64];
    __shared__ float br1s[64];
    __shared__ float basw_s[8][96];
    __shared__ int   slk[KTOT];
    __shared__ float sfn[KTOT];

    int tid = threadIdx.x;
    int wid = tid >> 5, lane = tid & 31;

    if (tid == 0) build_tab(slk, sfn, nullptr);
    for (int i = tid; i < NRADB * 64; i += 256) Wr1s[i] = Wr1[i];
    if (tid < 64) br1s[tid] = br1[tid];
    __syncthreads();

    int e0 = blockIdx.x * 32 + wid * 4;
    float* basw = basw_s[wid];

    float rE = 0.f, uxE = 0.f, uyE = 0.f, uzE = 0.f, fcE = 0.f;
    if (lane < 4) {
        int e = e0 + lane;
        float x = rij[e * 3], y = rij[e * 3 + 1], z = rij[e * 3 + 2];
        float r = sqrtf(x * x + y * y + z * z);
        float inv = 1.f / r;
        rE = r;
        uxE = x * inv + 1e-12f;
        uyE = y * inv + 1e-12f;
        uzE = z * inv + 1e-12f;
        float rc = fminf(r, 6.f);
        fcE = 0.5f * (cosf(rc * 0.52359877559829887f) + 1.f);
    }
    {
        int ge = lane >> 3;
        float rB  = __shfl_sync(0xffffffffu, rE, ge);
        float fcB = __shfl_sync(0xffffffffu, fcE, ge);
#pragma unroll
        for (int q = 0; q < 3; q++) {
            int k = (lane & 7) + q * 8;
            float d = rB - (6.f / 23.f) * (float)k;
            basw[ge * 24 + k] = expf(-8.f * d * d) * fcB;
        }
    }
    __syncwarp();
    {
        float a0[4], a1[4];
#pragma unroll
        for (int e = 0; e < 4; e++) { a0[e] = 0.f; a1[e] = 0.f; }
#pragma unroll 6
        for (int k = 0; k < NRADB; k++) {
            float2 w = *(const float2*)&Wr1s[k * 64 + 2 * lane];
            float b0 = basw[k], b1 = basw[24 + k], b2 = basw[48 + k], b3 = basw[72 + k];
            a0[0] += b0 * w.x; a1[0] += b0 * w.y;
            a0[1] += b1 * w.x; a1[1] += b1 * w.y;
            a0[2] += b2 * w.x; a1[2] += b2 * w.y;
            a0[3] += b3 * w.x; a1[3] += b3 * w.y;
        }
        float2 bb = *(const float2*)&br1s[2 * lane];
#pragma unroll
        for (int e = 0; e < 4; e++) {
            float h0 = silu_f(a0[e] + bb.x);
            float h1 = silu_f(a1[e] + bb.y);
            __nv_bfloat16 H0 = __float2bfloat16(h0);
            __nv_bfloat16 H1 = __float2bfloat16(h1);
            size_t off = (size_t)(e0 + e) * 64 + 2 * lane;
            *(__nv_bfloat162*)&d_hh[off] = __halves2bfloat162(H0, H1);
            *(__nv_bfloat162*)&d_hl[off] = __halves2bfloat162(
                __float2bfloat16(h0 - __bfloat162float(H0)),
                __float2bfloat16(h1 - __bfloat162float(H1)));
        }
    }
#pragma unroll
    for (int e4 = 0; e4 < 4; e4++) {
        float ux = __shfl_sync(0xffffffffu, uxE, e4);
        float uy = __shfl_sync(0xffffffffu, uyE, e4);
        float uz = __shfl_sync(0xffffffffu, uzE, e4);
#pragma unroll
        for (int q = 0; q < 3; q++) {
            int k = lane + q * 32;
            if (k < KTOT) {
                int pk = slk[k];
                d_gv[(size_t)(e0 + e4) * 72 + k] = sfn[k] *
                    powi(ux, pk & 255) * powi(uy, (pk >> 8) & 255) * powi(uz, pk >> 16);
            }
        }
    }
}

// ---------------- MLP2 GEMM: rad = silu(h @ Wr2p + b), 3-pass bf16 split ----------------
// BM=64 (smem 54KB, launch_bounds(256,3)). Warp tile m16 x n64.
#define E2_LDA 72
#define E2_AH 0
#define E2_AL 9216
#define E2_BH 18432
#define E2_BL 36864
#define E2_SMEM 55296
__global__ __launch_bounds__(256, 3) void mlp2_gemm_kernel(
    const __nv_bfloat16* __restrict__ hh, const __nv_bfloat16* __restrict__ hl,
    float* __restrict__ rad)
{
    extern __shared__ char smem[];
    uint32_t sb = smem_u32(smem);
    int tid = threadIdx.x;
    int warp = tid >> 5, lane = tid & 31;
    int e0 = blockIdx.x * 64;

    for (int i = tid; i < 512; i += 256) {
        int row = i >> 3, ch = i & 7;
        size_t ga = (size_t)(e0 + row) * 64 + ch * 8;
        *(uint4*)(smem + E2_AH + row * 144 + ch * 16) = *(const uint4*)(hh + ga);
        *(uint4*)(smem + E2_AL + row * 144 + ch * 16) = *(const uint4*)(hl + ga);
    }
    for (int i = tid; i < 1024; i += 256) {
        int row = i >> 3, ch = i & 7;
        *(uint4*)(smem + E2_BH + row * 144 + ch * 16) = *(const uint4*)(d_Bt2_hi + row * 64 + ch * 8);
        *(uint4*)(smem + E2_BL + row * 144 + ch * 16) = *(const uint4*)(d_Bt2_lo + row * 64 + ch * 8);
    }
    __syncthreads();

    int m0 = (warp & 3) * 16;
    int n0 = (warp >> 2) * 64;
    int lrow = (lane & 7) + ((lane >> 3) & 1) * 8;
    int lcol = (lane >> 4) * 8;

    float acc[8][4];
#pragma unroll
    for (int j = 0; j < 8; j++)
#pragma unroll
        for (int q = 0; q < 4; q++) acc[j][q] = 0.f;

#pragma unroll
    for (int kst = 0; kst < 4; kst++) {
        int kcol = kst * 16 + lcol;
        uint32_t ah[4], al[4];
        ldsm4(ah, sb + E2_AH + ((m0 + lrow) * E2_LDA + kcol) * 2);
        ldsm4(al, sb + E2_AL + ((m0 + lrow) * E2_LDA + kcol) * 2);
#pragma unroll
        for (int nb = 0; nb < 4; nb++) {
            uint32_t th[4], tl[4];
            ldsm4(th, sb + E2_BH + ((n0 + nb * 16 + lrow) * E2_LDA + kcol) * 2);
            ldsm4(tl, sb + E2_BL + ((n0 + nb * 16 + lrow) * E2_LDA + kcol) * 2);
            uint32_t b0h[2] = {th[0], th[2]}, b1h[2] = {th[1], th[3]};
            uint32_t b0l[2] = {tl[0], tl[2]}, b1l[2] = {tl[1], tl[3]};
            mma16816(acc[2 * nb],     ah, b0h);
            mma16816(acc[2 * nb],     al, b0h);
            mma16816(acc[2 * nb],     ah, b0l);
            mma16816(acc[2 * nb + 1], ah, b1h);
            mma16816(acc[2 * nb + 1], al, b1h);
            mma16816(acc[2 * nb + 1], ah, b1l);
        }
    }

    int gid = lane >> 2, tig = lane & 3;
    int r0 = e0 + m0 + gid;
#pragma unroll
    for (int j = 0; j < 8; j++) {
        int cn = n0 + j * 8 + tig * 2;
        if (cn < 120) {
            float b0 = d_br2p[cn], b1 = d_br2p[cn + 1];
            *(float2*)(rad + (size_t)r0 * 120 + cn) =
                make_float2(silu_f(acc[j][0] + b0), silu_f(acc[j][1] + b1));
            *(float2*)(rad + (size_t)(r0 + 8) * 120 + cn) =
                make_float2(silu_f(acc[j][2] + b0), silu_f(acc[j][3] + b1));
        }
    }
}

// ---------------- per-atom moment kernel: seg-search + stage + phase B + features ----------------
__global__ __launch_bounds__(256) void moment_kernel(
    const float* __restrict__ rad, const float* __restrict__ gv,
    const float* __restrict__ Ws1, const float* __restrict__ bs1,
    const float* __restrict__ Ws2, const float* __restrict__ bs2,
    const int* __restrict__ species, const int* __restrict__ fia)
{
    __shared__ float rads[TILE * 120];
    __shared__ float gvs[TILE * 72];
    __shared__ float gis[70 * 24];
    __shared__ float hsp[32];
    __shared__ float slam[KTOT];
    __shared__ int   sbounds[2];

    int tid = threadIdx.x;
    int a = blockIdx.x;

    if (tid == 64) build_tab(nullptr, nullptr, slam);
    if (tid < 2) sbounds[tid] = seg_lower_bound(fia, a + tid);

    int sidx = species[a];
    if (tid < 32) hsp[tid] = silu_f(Ws1[sidx * 32 + tid] + bs1[tid]);
    __syncthreads();
    if (tid < EMBD) {
        float acc = bs2[tid];
        for (int i = 0; i < 32; i++) acc += hsp[i] * Ws2[i * EMBD + tid];
        d_emb[a * EMBD + tid] = acc;
    }

    bool actB = tid < 210;
    int kB = tid / 3, r0B = (tid % 3) * 8, cB = 0;
    if (actB) cB = (kB < 4) ? 1 : (kB < 14) ? 2 : (kB < 34) ? 3 : (kB < 69) ? 4 : 0;
    float accB[8];
#pragma unroll
    for (int q = 0; q < 8; q++) accB[q] = 0.f;

    int beg = sbounds[0], end = sbounds[1];

    for (int pos = beg; pos < end; pos += TILE) {
        int nE = min(TILE, end - pos);
        for (int i = tid; i < nE * 30; i += 256) {
            int row = i / 30, ch = i % 30;
            *(float4*)&rads[row * 120 + ch * 4] =
                *(const float4*)(rad + (size_t)(pos + row) * 120 + ch * 4);
        }
        for (int i = tid; i < nE * 18; i += 256) {
            int row = i / 18, ch = i % 18;
            *(float4*)&gvs[row * 72 + ch * 4] =
                *(const float4*)(gv + (size_t)(pos + row) * 72 + ch * 4);
        }
        __syncthreads();
        if (actB) {
            int base = cB * 24 + r0B;
            for (int e = 0; e < nE; e++) {
                float g = (kB < KTOT) ? gvs[e * 72 + kB] : 1.f;
                const float4* rp = (const float4*)&rads[e * 120 + base];
                float4 p0 = rp[0], p1 = rp[1];
                accB[0] += g * p0.x; accB[1] += g * p0.y;
                accB[2] += g * p0.z; accB[3] += g * p0.w;
                accB[4] += g * p1.x; accB[5] += g * p1.y;
                accB[6] += g * p1.z; accB[7] += g * p1.w;
            }
        }
        __syncthreads();
    }

    if (actB) {
#pragma unroll
        for (int q = 0; q < 8; q++) gis[kB * 24 + r0B + q] = accB[q];
    }
    __syncthreads();

    if (tid < FDIM) {
        int grp = tid / NRADB, r = tid % NRADB;
        float v;
        if (grp == 0) {
            v = gis[KTOT * 24 + r];
        } else {
            int iz = (grp - 1) >> 1;
            int neg = (grp - 1) & 1;
            float ssum = 0.f;
            for (int k = KOFF[iz]; k < KOFF[iz + 1]; k++) {
                float g = gis[k * 24 + r];
                ssum += g * g * (neg ? slam[k] : 1.f);
            }
            v = ssum * (1.0f / (float)(1 << iz));
        }
        d_feat[a * FDIM + tid] = v;
    }
}

// ---------------- Wa1 -> transposed bf16 hi/lo [256][3456] ----------------
__global__ void conv_w1_kernel(const float* __restrict__ Wa1) {
    __shared__ float t[32][33];
    int k0 = blockIdx.x * 32, n0 = blockIdx.y * 32;
    int tx = threadIdx.x, ty = threadIdx.y;   // 32 x 8
#pragma unroll
    for (int r = 0; r < 32; r += 8)
        t[ty + r][tx] = Wa1[(size_t)(k0 + ty + r) * 256 + n0 + tx];
    __syncthreads();
#pragma unroll
    for (int r = 0; r < 32; r += 8) {
        int n = n0 + ty + r, k = k0 + tx;
        float v = t[tx][ty + r];
        __nv_bfloat16 h = __float2bfloat16(v);
        d_Bt_hi[(size_t)n * KTOTAL + k] = h;
        d_Bt_lo[(size_t)n * KTOTAL + k] = __float2bfloat16(v - __bfloat162float(h));
    }
}

// ---------------- X = feat (x) emb -> bf16 hi/lo [2048][3456] ----------------
__global__ void xgen_kernel(const float* __restrict__ feat, const float* __restrict__ emb) {
    int t = blockIdx.x * blockDim.x + threadIdx.x;
    int a = t / 432, rem = t % 432;
    int k0 = rem * 8;
    float f = feat[a * FDIM + (k0 >> 4)];
    const float4* ep = (const float4*)(emb + a * EMBD + (k0 & 15));
    float4 e0 = ep[0], e1 = ep[1];
    float v[8] = {f * e0.x, f * e0.y, f * e0.z, f * e0.w,
                  f * e1.x, f * e1.y, f * e1.z, f * e1.w};
    uint4 uh, ul;
    uint32_t* ph = (uint32_t*)&uh;
    uint32_t* pl = (uint32_t*)&ul;
#pragma unroll
    for (int i = 0; i < 4; i++) {
        __nv_bfloat16 h0 = __float2bfloat16(v[2 * i]);
        __nv_bfloat16 h1 = __float2bfloat16(v[2 * i + 1]);
        __nv_bfloat162 hh = __halves2bfloat162(h0, h1);
        __nv_bfloat162 ll = __halves2bfloat162(
            __float2bfloat16(v[2 * i] - __bfloat162float(h0)),
            __float2bfloat16(v[2 * i + 1] - __bfloat162float(h1)));
        ph[i] = *(uint32_t*)&hh;
        pl[i] = *(uint32_t*)&ll;
    }
    *(uint4*)&d_Xh[(size_t)a * KTOTAL + k0] = uh;
    *(uint4*)&d_Xl[(size_t)a * KTOTAL + k0] = ul;
}

// ---------------- GEMM1: double-buffered ldmatrix mma pipeline ----------------
#define LDA 40
#define A_HI_O 0
#define A_LO_O 10240
#define B_HI_O 20480
#define B_LO_O 25600
#define SBUF   30720
__global__ __launch_bounds__(256) void gemm1_mma_kernel(
    const __nv_bfloat16* __restrict__ Xh, const __nv_bfloat16* __restrict__ Xl,
    const __nv_bfloat16* __restrict__ Bth, const __nv_bfloat16* __restrict__ Btl,
    float* __restrict__ outp)
{
    extern __shared__ char smem[];
    uint32_t sb = smem_u32(smem);
    int tid = threadIdx.x;
    int warp = tid >> 5, lane = tid & 31;
    int wm0 = (warp >> 1) * 32, wn0 = (warp & 1) * 32;
    int mtile = blockIdx.x, ntile = blockIdx.y, kseg = blockIdx.z;

    int lrow = (lane & 7) + ((lane >> 3) & 1) * 8;
    int lcol = (lane >> 4) * 8;

    int arow = tid >> 1, aq = tid & 1;
    int brow = tid >> 2, bq = tid & 3;
    size_t gA = (size_t)(mtile * 128 + arow) * KTOTAL;
    size_t gB = (size_t)(ntile * 64 + brow) * KTOTAL;

    uint4 vah0, vah1, val0, val1, vbh, vbl;
    auto ldg = [&](int it) {
        int k0 = (kseg * ITERS + it) * 32;
        vah0 = *(const uint4*)(Xh + gA + k0 + aq * 16);
        vah1 = *(const uint4*)(Xh + gA + k0 + aq * 16 + 8);
        val0 = *(const uint4*)(Xl + gA + k0 + aq * 16);
        val1 = *(const uint4*)(Xl + gA + k0 + aq * 16 + 8);
        vbh  = *(const uint4*)(Bth + gB + k0 + bq * 8);
        vbl  = *(const uint4*)(Btl + gB + k0 + bq * 8);
    };
    auto sts = [&](int buf) {
        char* base = smem + buf * SBUF;
        int ao = arow * 80 + aq * 32;
        *(uint4*)(base + A_HI_O + ao)      = vah0;
        *(uint4*)(base + A_HI_O + ao + 16) = vah1;
        *(uint4*)(base + A_LO_O + ao)      = val0;
        *(uint4*)(base + A_LO_O + ao + 16) = val1;
        int bo = brow * 80 + bq * 16;
        *(uint4*)(base + B_HI_O + bo) = vbh;
        *(uint4*)(base + B_LO_O + bo) = vbl;
    };

    float acc[2][4][4];
#pragma unroll
    for (int i = 0; i < 2; i++)
#pragma unroll
        for (int j = 0; j < 4; j++)
#pragma unroll
            for (int q = 0; q < 4; q++) acc[i][j][q] = 0.f;

    ldg(0);
    sts(0);
    __syncthreads();

    for (int it = 0; it < ITERS; it++) {
        int buf = it & 1;
        bool more = (it + 1) < ITERS;
        if (more) ldg(it + 1);
        uint32_t aH = sb + buf * SBUF + A_HI_O;
        uint32_t aL = sb + buf * SBUF + A_LO_O;
        uint32_t bH = sb + buf * SBUF + B_HI_O;
        uint32_t bL = sb + buf * SBUF + B_LO_O;
#pragma unroll
        for (int kk = 0; kk < 2; kk++) {
            int kcol = kk * 16 + lcol;
            uint32_t ah[2][4], al[2][4], bh[4][2], bl[4][2];
#pragma unroll
            for (int i = 0; i < 2; i++) {
                uint32_t off = (uint32_t)(((wm0 + i * 16 + lrow) * LDA + kcol) * 2);
                ldsm4(ah[i], aH + off);
                ldsm4(al[i], aL + off);
            }
#pragma unroll
            for (int j2 = 0; j2 < 2; j2++) {
                uint32_t off = (uint32_t)(((wn0 + j2 * 16 + lrow) * LDA + kcol) * 2);
                uint32_t t[4];
                ldsm4(t, bH + off);
                bh[2 * j2][0] = t[0]; bh[2 * j2 + 1][0] = t[1];
                bh[2 * j2][1] = t[2]; bh[2 * j2 + 1][1] = t[3];
                ldsm4(t, bL + off);
                bl[2 * j2][0] = t[0]; bl[2 * j2 + 1][0] = t[1];
                bl[2 * j2][1] = t[2]; bl[2 * j2 + 1][1] = t[3];
            }
#pragma unroll
            for (int i = 0; i < 2; i++)
#pragma unroll
                for (int j = 0; j < 4; j++) {
                    mma16816(acc[i][j], ah[i], bh[j]);
                    mma16816(acc[i][j], al[i], bh[j]);
                    mma16816(acc[i][j], ah[i], bl[j]);
                }
        }
        if (more) sts(buf ^ 1);
        __syncthreads();
    }

    float* dst = outp + (size_t)kseg * NATOM * 256;
    int gid = lane >> 2, tig = lane & 3;
#pragma unroll
    for (int i = 0; i < 2; i++) {
        int r0 = mtile * 128 + wm0 + i * 16 + gid;
#pragma unroll
        for (int j = 0; j < 4; j++) {
            int cn = ntile * 64 + wn0 + j * 8 + tig * 2;
            *(float2*)(dst + (size_t)r0 * 256 + cn) = make_float2(acc[i][j][0], acc[i][j][1]);
            *(float2*)(dst + (size_t)(r0 + 8) * 256 + cn) = make_float2(acc[i][j][2], acc[i][j][3]);
        }
    }
}

__global__ void bias_silu_kernel(const float* __restrict__ ba1) {
    int i = blockIdx.x * blockDim.x + threadIdx.x;
    float s = d_h1parts[i] + d_h1parts[i + NATOM * 256]
            + d_h1parts[i + 2 * NATOM * 256] + d_h1parts[i + 3 * NATOM * 256];
    d_h1[i] = silu_f(s + ba1[i & 255]);
}

// ---------------- fp32 GEMM2 + bias + silu (128 CTAs) ----------------
__global__ __launch_bounds__(256) void gemm_silu_k(
    const float* __restrict__ A, const float* __restrict__ B,
    const float* __restrict__ bias, float* __restrict__ C,
    int M, int N, int K)
{
    const int BM = 32, BN = 64, BK = 32;
    __shared__ float As[BK][BM + 1];
    __shared__ float Bs[BK][BN + 1];
    int tid = threadIdx.x;
    int tx = tid & 15, ty = tid >> 4;   // 16 x 16
    int row0 = blockIdx.x * BM, col0 = blockIdx.y * BN;
    float accum[2][4];
#pragma unroll
    for (int i = 0; i < 2; i++)
#pragma unroll
        for (int j = 0; j < 4; j++) accum[i][j] = 0.f;

    for (int k0 = 0; k0 < K; k0 += BK) {
        for (int i = tid; i < BM * BK; i += 256) {
            int m = i / BK, k = i % BK;
            As[k][m] = A[(size_t)(row0 + m) * K + k0 + k];
        }
        for (int i = tid; i < BK * BN; i += 256) {
            int k = i / BN, n = i % BN;
            Bs[k][n] = B[(size_t)(k0 + k) * N + col0 + n];
        }
        __syncthreads();
#pragma unroll
        for (int k = 0; k < BK; k++) {
            float av[2], bv[4];
#pragma unroll
            for (int i = 0; i < 2; i++) av[i] = As[k][ty * 2 + i];
#pragma unroll
            for (int j = 0; j < 4; j++) bv[j] = Bs[k][tx * 4 + j];
#pragma unroll
            for (int i = 0; i < 2; i++)
#pragma unroll
                for (int j = 0; j < 4; j++) accum[i][j] += av[i] * bv[j];
        }
        __syncthreads();
    }
#pragma unroll
    for (int i = 0; i < 2; i++) {
        int row = row0 + ty * 2 + i;
#pragma unroll
        for (int j = 0; j < 4; j++) {
            int col = col0 + tx * 4 + j;
            C[(size_t)row * N + col] = silu_f(accum[i][j] + bias[col]);
        }
    }
}

// ---------------- final reduction ----------------
__global__ void zero_out_k(float* out) { out[0] = 0.f; }

__global__ void final_kernel(const float* __restrict__ Wa3,
                             const float* __restrict__ ba3, float* out) {
    int gt = blockIdx.x * blockDim.x + threadIdx.x;
    int a = gt >> 5, lane = gt & 31;
    if (a < NATOM) {
        float s = 0.f;
#pragma unroll
        for (int i = lane; i < 128; i += 32) s += d_h2[a * 128 + i] * Wa3[i];
#pragma unroll
        for (int o = 16; o; o >>= 1) s += __shfl_xor_sync(0xffffffffu, s, o);
        if (lane == 0) atomicAdd(out, s + ba3[0]);
    }
}

// ---------------- launch ----------------
extern "C" void kernel_launch(void* const* d_in, const int* in_sizes, int n_in,
                              void* d_out, int out_size) {
    (void)in_sizes; (void)n_in; (void)out_size;
    const float* rij = (const float*)d_in[0];
    const float* Wr1 = (const float*)d_in[1];
    const float* br1 = (const float*)d_in[2];
    const float* Wr2 = (const float*)d_in[3];
    const float* br2 = (const float*)d_in[4];
    const float* Ws1 = (const float*)d_in[5];
    const float* bs1 = (const float*)d_in[6];
    const float* Ws2 = (const float*)d_in[7];
    const float* bs2 = (const float*)d_in[8];
    const float* Wa1 = (const float*)d_in[9];
    const float* ba1 = (const float*)d_in[10];
    const float* Wa2 = (const float*)d_in[11];
    const float* ba2 = (const float*)d_in[12];
    const float* Wa3 = (const float*)d_in[13];
    const float* ba3 = (const float*)d_in[14];
    const int*   fia     = (const int*)d_in[15];
    const int*   species = (const int*)d_in[16];
    float* out = (float*)d_out;

    void *p_feat, *p_emb, *p_parts, *p_h1, *p_h2, *p_bth, *p_btl, *p_xh, *p_xl;
    void *p_hh, *p_hl, *p_gv, *p_rad;
    cudaGetSymbolAddress(&p_feat,  d_feat);
    cudaGetSymbolAddress(&p_emb,   d_emb);
    cudaGetSymbolAddress(&p_parts, d_h1parts);
    cudaGetSymbolAddress(&p_h1,    d_h1);
    cudaGetSymbolAddress(&p_h2,    d_h2);
    cudaGetSymbolAddress(&p_bth,   d_Bt_hi);
    cudaGetSymbolAddress(&p_btl,   d_Bt_lo);
    cudaGetSymbolAddress(&p_xh,    d_Xh);
    cudaGetSymbolAddress(&p_xl,    d_Xl);
    cudaGetSymbolAddress(&p_hh,    d_hh);
    cudaGetSymbolAddress(&p_hl,    d_hl);
    cudaGetSymbolAddress(&p_gv,    d_gv);
    cudaGetSymbolAddress(&p_rad,   d_rad);

    conv_w2_kernel<<<(128 * 64 + 255) / 256, 256>>>(Wr2, br2);      // 0
    edge_kernel<<<NEDGE / 32, 256>>>(rij, Wr1, br1);                // 1

    cudaFuncSetAttribute(mlp2_gemm_kernel, cudaFuncAttributeMaxDynamicSharedMemorySize, E2_SMEM);
    mlp2_gemm_kernel<<<NEDGE / 64, 256, E2_SMEM>>>(                 // 2
        (const __nv_bfloat16*)p_hh, (const __nv_bfloat16*)p_hl, (float*)p_rad);

    moment_kernel<<<NATOM, 256>>>((const float*)p_rad, (const float*)p_gv,
                                  Ws1, bs1, Ws2, bs2, species, fia);  // 3 (profiled)

    conv_w1_kernel<<<dim3(KTOTAL / 32, 256 / 32), dim3(32, 8)>>>(Wa1);  // 4
    xgen_kernel<<<NATOM * 432 / 256, 256>>>((const float*)p_feat, (const float*)p_emb);  // 5

    const int G1SMEM = 2 * SBUF;
    cudaFuncSetAttribute(gemm1_mma_kernel, cudaFuncAttributeMaxDynamicSharedMemorySize, G1SMEM);
    gemm1_mma_kernel<<<dim3(NATOM / 128, 256 / 64, KSPLIT), 256, G1SMEM>>>(
        (const __nv_bfloat16*)p_xh, (const __nv_bfloat16*)p_xl,
        (const __nv_bfloat16*)p_bth, (const __nv_bfloat16*)p_btl,
        (float*)p_parts);                                           // 6

    bias_silu_kernel<<<NATOM * 256 / 256, 256>>>(ba1);              // 7

    gemm_silu_k<<<dim3(NATOM / 32, 128 / 64), 256>>>(
        (const float*)p_h1, Wa2, ba2, (float*)p_h2, NATOM, 128, 256);  // 8

    zero_out_k<<<1, 1>>>(out);                                      // 9
    final_kernel<<<NATOM * 32 / 256, 256>>>(Wa3, ba3, out);         // 10
}